// round 15
// baseline (speedup 1.0000x reference)
#include <cuda_runtime.h>
#include <cuda_fp16.h>
#include <cstdint>

#define S_LEN 8192
#define HID   1024
#define NH    16
#define DH    64
#define WIN   128
#define CHUNK 128
#define KEYS  384
#define ROWE  72            // fp16 elems per padded row (144 B)
#define ROWB  (ROWE * 2)
#define PLANE (KEYS * ROWB)      // 55296 B
#define SMEM_TOTAL (3 * PLANE)   // 165888 B  (K_hi fp16, K fp8, V fp16)
#define LOG2E 1.4426950408889634f
#define RSCALE 1024.0f
#define INV_RSCALE 0.0009765625f

// ---------- PTX wrappers ----------
__device__ __forceinline__ void ldsm4(uint32_t addr, uint32_t r[4]) {
    asm volatile("ldmatrix.sync.aligned.m8n8.x4.shared.b16 {%0,%1,%2,%3}, [%4];"
        : "=r"(r[0]), "=r"(r[1]), "=r"(r[2]), "=r"(r[3]) : "r"(addr));
}
__device__ __forceinline__ void ldsm4t(uint32_t addr, uint32_t r[4]) {
    asm volatile("ldmatrix.sync.aligned.m8n8.x4.trans.shared.b16 {%0,%1,%2,%3}, [%4];"
        : "=r"(r[0]), "=r"(r[1]), "=r"(r[2]), "=r"(r[3]) : "r"(addr));
}
__device__ __forceinline__ void mma16816h(float* c, const uint32_t* a, uint32_t b0, uint32_t b1) {
    asm volatile("mma.sync.aligned.m16n8k16.row.col.f32.f16.f16.f32 "
        "{%0,%1,%2,%3}, {%4,%5,%6,%7}, {%8,%9}, {%0,%1,%2,%3};"
        : "+f"(c[0]), "+f"(c[1]), "+f"(c[2]), "+f"(c[3])
        : "r"(a[0]), "r"(a[1]), "r"(a[2]), "r"(a[3]), "r"(b0), "r"(b1));
}
__device__ __forceinline__ void mma16832e4(float* c, const uint32_t* a, uint32_t b0, uint32_t b1) {
    asm volatile("mma.sync.aligned.m16n8k32.row.col.f32.e4m3.e4m3.f32 "
        "{%0,%1,%2,%3}, {%4,%5,%6,%7}, {%8,%9}, {%0,%1,%2,%3};"
        : "+f"(c[0]), "+f"(c[1]), "+f"(c[2]), "+f"(c[3])
        : "r"(a[0]), "r"(a[1]), "r"(a[2]), "r"(a[3]), "r"(b0), "r"(b1));
}
__device__ __forceinline__ float ex2(float x) {
    float y; asm("ex2.approx.f32 %0, %1;" : "=f"(y) : "f"(x)); return y;
}
// split two floats into packed-fp16 hi word + residual lo word (x0 in low half)
__device__ __forceinline__ void split_pack_h(float x0, float x1, uint32_t& hi, uint32_t& lo) {
    __half2 h2 = __floats2half2_rn(x0, x1);
    float2  bk = __half22float2(h2);
    __half2 l2 = __floats2half2_rn(x0 - bk.x, x1 - bk.y);
    hi = *reinterpret_cast<uint32_t*>(&h2);
    lo = *reinterpret_cast<uint32_t*>(&l2);
}
__device__ __forceinline__ uint32_t pack_h(float x0, float x1) {
    __half2 h2 = __floats2half2_rn(x0, x1);
    return *reinterpret_cast<uint32_t*>(&h2);
}
// pack 4 floats into 4 e4m3 bytes (a -> byte0 ... d -> byte3)
__device__ __forceinline__ uint32_t pack_e4(float a, float b, float c, float d) {
    uint16_t lo, hi;
    asm("cvt.rn.satfinite.e4m3x2.f32 %0, %1, %2;" : "=h"(lo) : "f"(b), "f"(a));
    asm("cvt.rn.satfinite.e4m3x2.f32 %0, %1, %2;" : "=h"(hi) : "f"(d), "f"(c));
    return (uint32_t)lo | ((uint32_t)hi << 16);
}

extern __shared__ char sm[];

// ---- QK hi term: fp16 Qh x Kh (16 MMAs), zero-inits S ----
#define QK_HI(S, TI) do {                                                       \
    const int kloc0q = (t0 + (TI)) * 32;                                        \
    _Pragma("unroll")                                                           \
    for (int j = 0; j < 4; j++)                                                 \
        _Pragma("unroll")                                                       \
        for (int r = 0; r < 4; r++) S[j][r] = 0.f;                              \
    _Pragma("unroll")                                                           \
    for (int kg = 0; kg < 4; kg++) {                                            \
        _Pragma("unroll")                                                       \
        for (int np = 0; np < 2; np++) {                                        \
            int keyrow = kloc0q + np * 16 + (mm >> 1) * 8 + lm7;                \
            int dim    = kg * 16 + (mm & 1) * 8;                                \
            uint32_t off = (uint32_t)(keyrow * ROWB + dim * 2);                 \
            uint32_t kbh[4];                                                    \
            ldsm4(K_HI + off, kbh);                                             \
            mma16816h(S[2*np],   aqh[kg], kbh[0], kbh[1]);                      \
            mma16816h(S[2*np+1], aqh[kg], kbh[2], kbh[3]);                      \
        }                                                                       \
    }                                                                           \
} while (0)

// ---- QK correction: fp8 k=128 fused cross-terms (16 MMAs) + combine ----
#define QK_CORR(S, TI) do {                                                     \
    const int kloc0q = (t0 + (TI)) * 32;                                        \
    float Sc[4][4];                                                             \
    _Pragma("unroll")                                                           \
    for (int j = 0; j < 4; j++)                                                 \
        _Pragma("unroll")                                                       \
        for (int r = 0; r < 4; r++) Sc[j][r] = 0.f;                             \
    _Pragma("unroll")                                                           \
    for (int kbg = 0; kbg < 4; kbg++) {                                         \
        _Pragma("unroll")                                                       \
        for (int np = 0; np < 2; np++) {                                        \
            int keyrow = kloc0q + np * 16 + (mm >> 1) * 8 + lm7;                \
            int kbyte  = kbg * 32 + (mm & 1) * 16;                              \
            uint32_t off = (uint32_t)(keyrow * ROWB + kbyte);                   \
            uint32_t kb8[4];                                                    \
            ldsm4(K_F8 + off, kb8);                                             \
            mma16832e4(Sc[2*np],   aq8[kbg], kb8[0], kb8[1]);                   \
            mma16832e4(Sc[2*np+1], aq8[kbg], kb8[2], kb8[3]);                   \
        }                                                                       \
    }                                                                           \
    _Pragma("unroll")                                                           \
    for (int j = 0; j < 4; j++)                                                 \
        _Pragma("unroll")                                                       \
        for (int r = 0; r < 4; r++) S[j][r] = fmaf(Sc[j][r], INV_RSCALE, S[j][r]); \
} while (0)

// ---- mask + cross-quad max + rescale factors ----
#define SM_MAX(S, TI, MN0, MN1, SC0, SC1) do {                                  \
    const int kabs = base + (t0 + (TI)) * 32;                                   \
    const bool edge = ((TI) == 0) | ((TI) == 8) | (kabs < 0) | (kabs + 31 >= S_LEN); \
    if (edge) {                                                                 \
        _Pragma("unroll")                                                       \
        for (int j = 0; j < 4; j++) {                                           \
            _Pragma("unroll")                                                   \
            for (int r = 0; r < 4; r++) {                                       \
                int key  = kabs + 8 * j + 2 * tt + (r & 1);                     \
                int qrow = qa0 + g + ((r >> 1) << 3);                           \
                bool valid = (key >= 0) && (key < S_LEN) &&                     \
                             (key >= qrow - WIN) && (key <= qrow + WIN);        \
                if (!valid) S[j][r] = -1e30f;                                   \
            }                                                                   \
        }                                                                       \
    }                                                                           \
    float mt0 = fmaxf(fmaxf(S[0][0], S[0][1]), fmaxf(S[1][0], S[1][1]));        \
    float mt1 = fmaxf(fmaxf(S[0][2], S[0][3]), fmaxf(S[1][2], S[1][3]));        \
    mt0 = fmaxf(mt0, fmaxf(fmaxf(S[2][0], S[2][1]), fmaxf(S[3][0], S[3][1]))); \
    mt1 = fmaxf(mt1, fmaxf(fmaxf(S[2][2], S[2][3]), fmaxf(S[3][2], S[3][3]))); \
    mt0 = fmaxf(mt0, __shfl_xor_sync(0xffffffffu, mt0, 1));                     \
    mt1 = fmaxf(mt1, __shfl_xor_sync(0xffffffffu, mt1, 1));                     \
    mt0 = fmaxf(mt0, __shfl_xor_sync(0xffffffffu, mt0, 2));                     \
    mt1 = fmaxf(mt1, __shfl_xor_sync(0xffffffffu, mt1, 2));                     \
    MN0 = fmaxf(mx[0], mt0); MN1 = fmaxf(mx[1], mt1);                           \
    SC0 = ex2(mx[0] - MN0);  SC1 = ex2(mx[1] - MN1);                            \
    mx[0] = MN0; mx[1] = MN1;                                                   \
    rs[0] *= SC0; rs[1] *= SC1;                                                 \
} while (0)

// ---- exp + rowsum + of-rescale + fp16 P pack + PV (16 MMAs) ----
#define SM_EXPPV(S, TI, MN0, MN1, SC0, SC1) do {                                \
    const int kloc0p = (t0 + (TI)) * 32;                                        \
    _Pragma("unroll")                                                           \
    for (int j = 0; j < 4; j++) {                                               \
        float e0 = ex2(S[j][0] - MN0);                                          \
        float e1 = ex2(S[j][1] - MN0);                                          \
        float e2 = ex2(S[j][2] - MN1);                                          \
        float e3 = ex2(S[j][3] - MN1);                                          \
        rs[0] += e0 + e1; rs[1] += e2 + e3;                                     \
        S[j][0] = e0; S[j][1] = e1; S[j][2] = e2; S[j][3] = e3;                 \
    }                                                                           \
    _Pragma("unroll")                                                           \
    for (int j = 0; j < 8; j++) {                                               \
        of[j][0] *= SC0; of[j][1] *= SC0;                                       \
        of[j][2] *= SC1; of[j][3] *= SC1;                                       \
    }                                                                           \
    uint32_t pah[2][4];                                                         \
    _Pragma("unroll")                                                           \
    for (int kg = 0; kg < 2; kg++) {                                            \
        pah[kg][0] = pack_h(S[2*kg][0],   S[2*kg][1]);                          \
        pah[kg][1] = pack_h(S[2*kg][2],   S[2*kg][3]);                          \
        pah[kg][2] = pack_h(S[2*kg+1][0], S[2*kg+1][1]);                        \
        pah[kg][3] = pack_h(S[2*kg+1][2], S[2*kg+1][3]);                        \
    }                                                                           \
    _Pragma("unroll")                                                           \
    for (int kg = 0; kg < 2; kg++) {                                            \
        _Pragma("unroll")                                                       \
        for (int jp = 0; jp < 4; jp++) {                                        \
            int keyrow = kloc0p + kg * 16 + (mm & 1) * 8 + lm7;                 \
            int dim    = (jp * 2 + (mm >> 1)) * 8;                              \
            uint32_t off = (uint32_t)(keyrow * ROWB + dim * 2);                 \
            uint32_t vb[4];                                                     \
            ldsm4t(V_PL + off, vb);                                             \
            mma16816h(of[2*jp],   pah[kg], vb[0], vb[1]);                       \
            mma16816h(of[2*jp+1], pah[kg], vb[2], vb[3]);                       \
        }                                                                       \
    }                                                                           \
} while (0)

__global__ __launch_bounds__(256, 1)
void swa_mma_kernel(const float* __restrict__ Q, const float* __restrict__ K,
                    const float* __restrict__ V, float* __restrict__ O) {
    const int tid  = threadIdx.x;
    const int warp = tid >> 5;
    const int lane = tid & 31;
    const int g    = lane >> 2;
    const int tt   = lane & 3;
    const int mm   = lane >> 3;
    const int lm7  = lane & 7;

    const int c = blockIdx.x, h = blockIdx.y, b = blockIdx.z;
    const int cb = c * CHUNK;
    const int base = cb - WIN;

    const uint32_t SB   = (uint32_t)__cvta_generic_to_shared(sm);
    const uint32_t K_HI = SB;
    const uint32_t K_F8 = SB + PLANE;
    const uint32_t V_PL = SB + 2 * PLANE;

    // ---------------- Q fragments ----------------
    // fp16 hi frags (cols 2tt pattern), scaled by log2e
    uint32_t aqh[4][4];
    // fp8 frags: aq8[0..1] = e4m3(qh), aq8[2..3] = e4m3(1024*ql), cols 4tt pattern
    uint32_t aq8[4][4];
    {
        const int qrow = cb + warp * 16 + g;
        const float* qp = Q + ((size_t)(b * S_LEN + qrow) * HID) + h * DH;
        #pragma unroll
        for (int kg = 0; kg < 4; kg++) {
            const int col0 = kg * 16 + 2 * tt;
            float2 x0 = *(const float2*)(qp + col0);
            float2 x1 = *(const float2*)(qp + 8 * HID + col0);
            float2 x2 = *(const float2*)(qp + col0 + 8);
            float2 x3 = *(const float2*)(qp + 8 * HID + col0 + 8);
            aqh[kg][0] = pack_h(x0.x * LOG2E, x0.y * LOG2E);
            aqh[kg][1] = pack_h(x1.x * LOG2E, x1.y * LOG2E);
            aqh[kg][2] = pack_h(x2.x * LOG2E, x2.y * LOG2E);
            aqh[kg][3] = pack_h(x3.x * LOG2E, x3.y * LOG2E);
        }
        #pragma unroll
        for (int rw = 0; rw < 2; rw++) {
            const float* qr = qp + rw * 8 * HID;
            #pragma unroll
            for (int cc = 0; cc < 4; cc++) {
                float4 q4 = *(const float4*)(qr + cc * 16 + 4 * tt);
                float s0 = q4.x * LOG2E, s1 = q4.y * LOG2E;
                float s2 = q4.z * LOG2E, s3 = q4.w * LOG2E;
                __half2 ha = __floats2half2_rn(s0, s1), hb = __floats2half2_rn(s2, s3);
                float2 fa = __half22float2(ha), fb = __half22float2(hb);
                aq8[cc >> 1][(cc & 1) * 2 + rw] = pack_e4(fa.x, fa.y, fb.x, fb.y);
                aq8[2 + (cc >> 1)][(cc & 1) * 2 + rw] =
                    pack_e4((s0 - fa.x) * RSCALE, (s1 - fa.y) * RSCALE,
                            (s2 - fb.x) * RSCALE, (s3 - fb.y) * RSCALE);
            }
        }
    }

    // ---------------- Stage K (fp16 hi + fp8 [kl*1024 | kh]) and V ----------------
    {
        #pragma unroll
        for (int it = 0; it < 24; it++) {
            int j   = tid + it * 256;
            int row = j >> 4;
            int c4  = (j & 15) * 4;
            int key = base + row;
            float4 k4 = make_float4(0.f, 0.f, 0.f, 0.f), v4 = k4;
            if (key >= 0 && key < S_LEN) {
                size_t off = ((size_t)(b * S_LEN + key) * HID) + h * DH + c4;
                k4 = *(const float4*)(K + off);
                v4 = *(const float4*)(V + off);
            }
            __half2 ha = __floats2half2_rn(k4.x, k4.y), hb = __floats2half2_rn(k4.z, k4.w);
            float2 fa = __half22float2(ha), fb = __half22float2(hb);
            int so = row * ROWB + c4 * 2;
            *(uint2*)(sm + so) = make_uint2(*reinterpret_cast<uint32_t*>(&ha),
                                            *reinterpret_cast<uint32_t*>(&hb));
            // fp8 plane: bytes [0,64) = e4m3(1024*kl), bytes [64,128) = e4m3(kh)
            *(uint32_t*)(sm + PLANE + row * ROWB + c4) =
                pack_e4((k4.x - fa.x) * RSCALE, (k4.y - fa.y) * RSCALE,
                        (k4.z - fb.x) * RSCALE, (k4.w - fb.y) * RSCALE);
            *(uint32_t*)(sm + PLANE + row * ROWB + 64 + c4) =
                pack_e4(fa.x, fa.y, fb.x, fb.y);
            *(uint2*)(sm + 2 * PLANE + so) =
                make_uint2(pack_h(v4.x, v4.y), pack_h(v4.z, v4.w));
        }
    }
    __syncthreads();

    // ---------------- Main loop: A/B bracketed, hi/corr split ----------------
    float of[8][4];
    #pragma unroll
    for (int j = 0; j < 8; j++)
        #pragma unroll
        for (int r = 0; r < 4; r++) of[j][r] = 0.f;
    float rs[2] = {0.f, 0.f};
    float mx[2] = {-60000.f, -60000.f};

    const int t0  = warp >> 1;
    const int qa0 = cb + warp * 16;

    float sA[4][4], sB[4][4];
    float mn0, mn1, sc0, sc1;

    QK_HI(sA, 0);
    QK_CORR(sA, 0);
    #pragma unroll 1
    for (int ii = 0; ii < 4; ii++) {
        QK_HI(sB, 2 * ii + 1);
        SM_MAX(sA, 2 * ii, mn0, mn1, sc0, sc1);
        QK_CORR(sB, 2 * ii + 1);
        SM_EXPPV(sA, 2 * ii, mn0, mn1, sc0, sc1);
        QK_HI(sA, 2 * ii + 2);
        SM_MAX(sB, 2 * ii + 1, mn0, mn1, sc0, sc1);
        QK_CORR(sA, 2 * ii + 2);
        SM_EXPPV(sB, 2 * ii + 1, mn0, mn1, sc0, sc1);
    }
    SM_MAX(sA, 8, mn0, mn1, sc0, sc1);
    SM_EXPPV(sA, 8, mn0, mn1, sc0, sc1);

    // ---------------- Epilogue ----------------
    rs[0] += __shfl_xor_sync(0xffffffffu, rs[0], 1);
    rs[0] += __shfl_xor_sync(0xffffffffu, rs[0], 2);
    rs[1] += __shfl_xor_sync(0xffffffffu, rs[1], 1);
    rs[1] += __shfl_xor_sync(0xffffffffu, rs[1], 2);
    const float inv_lo = 1.f / rs[0];
    const float inv_hi = 1.f / rs[1];

    const int q_lo = qa0 + g;
    const int q_hi = q_lo + 8;
    #pragma unroll
    for (int j = 0; j < 8; j++) {
        int col = h * DH + 8 * j + 2 * tt;
        size_t off_lo = ((size_t)(b * S_LEN + q_lo) * HID) + col;
        size_t off_hi = ((size_t)(b * S_LEN + q_hi) * HID) + col;
        *(float2*)(O + off_lo) = make_float2(of[j][0] * inv_lo, of[j][1] * inv_lo);
        *(float2*)(O + off_hi) = make_float2(of[j][2] * inv_hi, of[j][3] * inv_hi);
    }
}

extern "C" void kernel_launch(void* const* d_in, const int* in_sizes, int n_in,
                              void* d_out, int out_size) {
    (void)n_in; (void)out_size;
    const float* Q = (const float*)d_in[0];
    const float* K = (const float*)d_in[1];
    const float* V = (const float*)d_in[2];
    float* O = (float*)d_out;

    int B = in_sizes[0] / (S_LEN * HID);
    cudaFuncSetAttribute(swa_mma_kernel,
                         cudaFuncAttributeMaxDynamicSharedMemorySize, SMEM_TOTAL);
    dim3 grid(S_LEN / CHUNK, NH, B);
    swa_mma_kernel<<<grid, 256, SMEM_TOTAL>>>(Q, K, V, O);
}

// round 16
// speedup vs baseline: 1.1557x; 1.1557x over previous
#include <cuda_runtime.h>
#include <cuda_fp16.h>
#include <cstdint>

#define S_LEN 8192
#define HID   1024
#define NH    16
#define DH    64
#define WIN   128
#define CHUNK 128
#define KEYS  384
#define ROWE  72            // fp16 elems per padded row (144 B); V cols 64-71 = ones block
#define ROWB  (ROWE * 2)
#define PLANE (KEYS * ROWB)      // 55296 B
#define SMEM_TOTAL (3 * PLANE)   // 165888 B  (K_hi, K_lo, V)
#define LOG2E 1.4426950408889634f

// ---------- PTX wrappers ----------
__device__ __forceinline__ void ldsm4(uint32_t addr, uint32_t r[4]) {
    asm volatile("ldmatrix.sync.aligned.m8n8.x4.shared.b16 {%0,%1,%2,%3}, [%4];"
        : "=r"(r[0]), "=r"(r[1]), "=r"(r[2]), "=r"(r[3]) : "r"(addr));
}
__device__ __forceinline__ void ldsm4t(uint32_t addr, uint32_t r[4]) {
    asm volatile("ldmatrix.sync.aligned.m8n8.x4.trans.shared.b16 {%0,%1,%2,%3}, [%4];"
        : "=r"(r[0]), "=r"(r[1]), "=r"(r[2]), "=r"(r[3]) : "r"(addr));
}
__device__ __forceinline__ void ldsm2t(uint32_t addr, uint32_t r[2]) {
    asm volatile("ldmatrix.sync.aligned.m8n8.x2.trans.shared.b16 {%0,%1}, [%2];"
        : "=r"(r[0]), "=r"(r[1]) : "r"(addr));
}
__device__ __forceinline__ void mma16816h(float* c, const uint32_t* a, uint32_t b0, uint32_t b1) {
    asm volatile("mma.sync.aligned.m16n8k16.row.col.f32.f16.f16.f32 "
        "{%0,%1,%2,%3}, {%4,%5,%6,%7}, {%8,%9}, {%0,%1,%2,%3};"
        : "+f"(c[0]), "+f"(c[1]), "+f"(c[2]), "+f"(c[3])
        : "r"(a[0]), "r"(a[1]), "r"(a[2]), "r"(a[3]), "r"(b0), "r"(b1));
}
__device__ __forceinline__ float ex2(float x) {
    float y; asm("ex2.approx.f32 %0, %1;" : "=f"(y) : "f"(x)); return y;
}
// exp2 of two floats -> packed fp16x2 (x0 in low half). -inf -> +0.
__device__ __forceinline__ uint32_t exp2h2(float x0, float x1) {
    __half2 h2 = __floats2half2_rn(x0, x1);
    uint32_t x = *reinterpret_cast<uint32_t*>(&h2), y;
    asm("ex2.approx.f16x2 %0, %1;" : "=r"(y) : "r"(x));
    return y;
}
// split two floats into packed-fp16 hi word + residual lo word (x0 in low half)
__device__ __forceinline__ void split_pack_h(float x0, float x1, uint32_t& hi, uint32_t& lo) {
    __half2 h2 = __floats2half2_rn(x0, x1);
    float2  bk = __half22float2(h2);
    __half2 l2 = __floats2half2_rn(x0 - bk.x, x1 - bk.y);
    hi = *reinterpret_cast<uint32_t*>(&h2);
    lo = *reinterpret_cast<uint32_t*>(&l2);
}
__device__ __forceinline__ uint32_t pack_h(float x0, float x1) {
    __half2 h2 = __floats2half2_rn(x0, x1);
    return *reinterpret_cast<uint32_t*>(&h2);
}

extern __shared__ char sm[];

// ---- QK of one 32-key tile into S (zeroed here), fp16 3-term ----
#define QK_TILE(S, TI) do {                                                     \
    const int kloc0q = (t0 + (TI)) * 32;                                        \
    _Pragma("unroll")                                                           \
    for (int j = 0; j < 4; j++)                                                 \
        _Pragma("unroll")                                                       \
        for (int r = 0; r < 4; r++) S[j][r] = 0.f;                              \
    _Pragma("unroll")                                                           \
    for (int kg = 0; kg < 4; kg++) {                                            \
        _Pragma("unroll")                                                       \
        for (int np = 0; np < 2; np++) {                                        \
            int keyrow = kloc0q + np * 16 + (mm >> 1) * 8 + lm7;                \
            int dim    = kg * 16 + (mm & 1) * 8;                                \
            uint32_t off = (uint32_t)(keyrow * ROWB + dim * 2);                 \
            uint32_t kbh[4], kbl[4];                                            \
            ldsm4(K_HI + off, kbh);                                             \
            ldsm4(K_LO + off, kbl);                                             \
            mma16816h(S[2*np],   aqh[kg], kbh[0], kbh[1]);                      \
            mma16816h(S[2*np],   aql[kg], kbh[0], kbh[1]);                      \
            mma16816h(S[2*np],   aqh[kg], kbl[0], kbl[1]);                      \
            mma16816h(S[2*np+1], aqh[kg], kbh[2], kbh[3]);                      \
            mma16816h(S[2*np+1], aql[kg], kbh[2], kbh[3]);                      \
            mma16816h(S[2*np+1], aqh[kg], kbl[2], kbl[3]);                      \
        }                                                                       \
    }                                                                           \
} while (0)

// ---- mask one tile's scores (edge tiles only do work) ----
#define MASK_S(S, TI) do {                                                      \
    const int kabs_m = base + (t0 + (TI)) * 32;                                 \
    const bool edge = ((TI) == 0) | ((TI) == 8) | (kabs_m < 0) | (kabs_m + 31 >= S_LEN); \
    if (edge) {                                                                 \
        _Pragma("unroll")                                                       \
        for (int j = 0; j < 4; j++) {                                           \
            _Pragma("unroll")                                                   \
            for (int r = 0; r < 4; r++) {                                       \
                int key  = kabs_m + 8 * j + 2 * tt + (r & 1);                   \
                int qrow = qa0 + g + ((r >> 1) << 3);                           \
                bool valid = (key >= 0) && (key < S_LEN) &&                     \
                             (key >= qrow - WIN) && (key <= qrow + WIN);        \
                if (!valid) S[j][r] = -1e30f;                                   \
            }                                                                   \
        }                                                                       \
    }                                                                           \
} while (0)

// ---- fmax tree over one tile into mt0/mt1 (accumulating) ----
#define MAXTREE(S, MT0, MT1) do {                                               \
    MT0 = fmaxf(MT0, fmaxf(fmaxf(S[0][0], S[0][1]), fmaxf(S[1][0], S[1][1]))); \
    MT1 = fmaxf(MT1, fmaxf(fmaxf(S[0][2], S[0][3]), fmaxf(S[1][2], S[1][3]))); \
    MT0 = fmaxf(MT0, fmaxf(fmaxf(S[2][0], S[2][1]), fmaxf(S[3][0], S[3][1]))); \
    MT1 = fmaxf(MT1, fmaxf(fmaxf(S[2][2], S[2][3]), fmaxf(S[3][2], S[3][3]))); \
} while (0)

// ---- finish max: shfl-reduce, update running max, rescale O and of9 ----
#define FINMAX(MT0, MT1) do {                                                   \
    MT0 = fmaxf(MT0, __shfl_xor_sync(0xffffffffu, MT0, 1));                     \
    MT1 = fmaxf(MT1, __shfl_xor_sync(0xffffffffu, MT1, 1));                     \
    MT0 = fmaxf(MT0, __shfl_xor_sync(0xffffffffu, MT0, 2));                     \
    MT1 = fmaxf(MT1, __shfl_xor_sync(0xffffffffu, MT1, 2));                     \
    mn0 = fmaxf(mx[0], MT0); mn1 = fmaxf(mx[1], MT1);                           \
    const float sc0 = ex2(mx[0] - mn0), sc1 = ex2(mx[1] - mn1);                 \
    mx[0] = mn0; mx[1] = mn1;                                                   \
    _Pragma("unroll")                                                           \
    for (int j = 0; j < 8; j++) {                                               \
        of[j][0] *= sc0; of[j][1] *= sc0;                                       \
        of[j][2] *= sc1; of[j][3] *= sc1;                                       \
    }                                                                           \
    of9[0] *= sc0; of9[1] *= sc0; of9[2] *= sc1; of9[3] *= sc1;                 \
} while (0)

// ---- exp (fp16x2) + PV incl. ones-column rowsum block ----
#define EXPPV(S, TI) do {                                                       \
    const int kloc0p = (t0 + (TI)) * 32;                                        \
    uint32_t pah[2][4];                                                         \
    _Pragma("unroll")                                                           \
    for (int kg = 0; kg < 2; kg++) {                                            \
        pah[kg][0] = exp2h2(S[2*kg][0]   - mn0, S[2*kg][1]   - mn0);            \
        pah[kg][1] = exp2h2(S[2*kg][2]   - mn1, S[2*kg][3]   - mn1);            \
        pah[kg][2] = exp2h2(S[2*kg+1][0] - mn0, S[2*kg+1][1] - mn0);            \
        pah[kg][3] = exp2h2(S[2*kg+1][2] - mn1, S[2*kg+1][3] - mn1);            \
    }                                                                           \
    _Pragma("unroll")                                                           \
    for (int kg = 0; kg < 2; kg++) {                                            \
        _Pragma("unroll")                                                       \
        for (int jp = 0; jp < 4; jp++) {                                        \
            int keyrow = kloc0p + kg * 16 + (mm & 1) * 8 + lm7;                 \
            int dim    = (jp * 2 + (mm >> 1)) * 8;                              \
            uint32_t off = (uint32_t)(keyrow * ROWB + dim * 2);                 \
            uint32_t vb[4];                                                     \
            ldsm4t(V_PL + off, vb);                                             \
            mma16816h(of[2*jp],   pah[kg], vb[0], vb[1]);                       \
            mma16816h(of[2*jp+1], pah[kg], vb[2], vb[3]);                       \
        }                                                                       \
        uint32_t vb2[2];                                                        \
        ldsm2t(V_PL + (uint32_t)((kloc0p + kg * 16 + (lane & 15)) * ROWB + 128), vb2); \
        mma16816h(of9, pah[kg], vb2[0], vb2[1]);                                \
    }                                                                           \
} while (0)

__global__ __launch_bounds__(256, 1)
void swa_mma_kernel(const float* __restrict__ Q, const float* __restrict__ K,
                    const float* __restrict__ V, float* __restrict__ O) {
    const int tid  = threadIdx.x;
    const int warp = tid >> 5;
    const int lane = tid & 31;
    const int g    = lane >> 2;
    const int tt   = lane & 3;
    const int mm   = lane >> 3;
    const int lm7  = lane & 7;

    const int c = blockIdx.x, h = blockIdx.y, b = blockIdx.z;
    const int cb = c * CHUNK;
    const int base = cb - WIN;

    const uint32_t SB   = (uint32_t)__cvta_generic_to_shared(sm);
    const uint32_t K_HI = SB;
    const uint32_t K_LO = SB + PLANE;
    const uint32_t V_PL = SB + 2 * PLANE;

    // ---------------- Q fragments: gmem -> regs, scaled by log2e (split fp16) ----------------
    uint32_t aqh[4][4], aql[4][4];
    {
        const int qrow = cb + warp * 16 + g;
        const float* qp = Q + ((size_t)(b * S_LEN + qrow) * HID) + h * DH;
        #pragma unroll
        for (int kg = 0; kg < 4; kg++) {
            const int col0 = kg * 16 + 2 * tt;
            float2 x0 = *(const float2*)(qp + col0);
            float2 x1 = *(const float2*)(qp + 8 * HID + col0);
            float2 x2 = *(const float2*)(qp + col0 + 8);
            float2 x3 = *(const float2*)(qp + 8 * HID + col0 + 8);
            split_pack_h(x0.x * LOG2E, x0.y * LOG2E, aqh[kg][0], aql[kg][0]);
            split_pack_h(x1.x * LOG2E, x1.y * LOG2E, aqh[kg][1], aql[kg][1]);
            split_pack_h(x2.x * LOG2E, x2.y * LOG2E, aqh[kg][2], aql[kg][2]);
            split_pack_h(x3.x * LOG2E, x3.y * LOG2E, aqh[kg][3], aql[kg][3]);
        }
    }

    // ---------------- Stage K (hi/lo) and V (+ones col 64), zero-filled out of range ----------
    {
        #pragma unroll
        for (int it = 0; it < 24; it++) {
            int j   = tid + it * 256;
            int row = j >> 4;
            int c4  = (j & 15) * 4;
            int key = base + row;
            float4 k4 = make_float4(0.f, 0.f, 0.f, 0.f), v4 = k4;
            if (key >= 0 && key < S_LEN) {
                size_t off = ((size_t)(b * S_LEN + key) * HID) + h * DH + c4;
                k4 = *(const float4*)(K + off);
                v4 = *(const float4*)(V + off);
            }
            int so = row * ROWB + c4 * 2;
            uint32_t h0, l0, h1, l1;
            split_pack_h(k4.x, k4.y, h0, l0);
            split_pack_h(k4.z, k4.w, h1, l1);
            *(uint2*)(sm + so)         = make_uint2(h0, h1);
            *(uint2*)(sm + PLANE + so) = make_uint2(l0, l1);
            *(uint2*)(sm + 2 * PLANE + so) =
                make_uint2(pack_h(v4.x, v4.y), pack_h(v4.z, v4.w));
            if ((j & 15) == 15)   // ones block: col64 = 1.0h, cols 65-71 = 0
                *(uint4*)(sm + 2 * PLANE + row * ROWB + 128) = make_uint4(0x3C00u, 0u, 0u, 0u);
        }
    }
    __syncthreads();

    // ---------------- Main loop: pairs share max/rescale; rowsum via ones column -------------
    float of[8][4];
    #pragma unroll
    for (int j = 0; j < 8; j++)
        #pragma unroll
        for (int r = 0; r < 4; r++) of[j][r] = 0.f;
    float of9[4] = {0.f, 0.f, 0.f, 0.f};
    float mx[2] = {-60000.f, -60000.f};
    float mn0, mn1;

    const int t0  = warp >> 1;
    const int qa0 = cb + warp * 16;

    float sA[4][4], sB[4][4];

    QK_TILE(sA, 0);
    #pragma unroll 1
    for (int ii = 0; ii < 4; ii++) {
        QK_TILE(sB, 2 * ii + 1);
        // joint max over pair (2ii, 2ii+1): one rescale per pair
        MASK_S(sA, 2 * ii);
        MASK_S(sB, 2 * ii + 1);
        {
            float mt0 = -1e30f, mt1 = -1e30f;
            MAXTREE(sA, mt0, mt1);
            MAXTREE(sB, mt0, mt1);
            FINMAX(mt0, mt1);
        }
        EXPPV(sA, 2 * ii);
        QK_TILE(sA, 2 * ii + 2);     // next pair's first tile brackets EXPPV(B)
        EXPPV(sB, 2 * ii + 1);
    }
    // tail tile 8 (in sA)
    MASK_S(sA, 8);
    {
        float mt0 = -1e30f, mt1 = -1e30f;
        MAXTREE(sA, mt0, mt1);
        FINMAX(mt0, mt1);
    }
    EXPPV(sA, 8);

    // ---------------- Epilogue: rowsum from ones column (col 64 -> tt==0, c[0]/c[2]) ---------
    const float l_lo = __shfl_sync(0xffffffffu, of9[0], lane & 28);
    const float l_hi = __shfl_sync(0xffffffffu, of9[2], lane & 28);
    const float inv_lo = 1.f / l_lo;
    const float inv_hi = 1.f / l_hi;

    const int q_lo = qa0 + g;
    const int q_hi = q_lo + 8;
    #pragma unroll
    for (int j = 0; j < 8; j++) {
        int col = h * DH + 8 * j + 2 * tt;
        size_t off_lo = ((size_t)(b * S_LEN + q_lo) * HID) + col;
        size_t off_hi = ((size_t)(b * S_LEN + q_hi) * HID) + col;
        *(float2*)(O + off_lo) = make_float2(of[j][0] * inv_lo, of[j][1] * inv_lo);
        *(float2*)(O + off_hi) = make_float2(of[j][2] * inv_hi, of[j][3] * inv_hi);
    }
}

extern "C" void kernel_launch(void* const* d_in, const int* in_sizes, int n_in,
                              void* d_out, int out_size) {
    (void)n_in; (void)out_size;
    const float* Q = (const float*)d_in[0];
    const float* K = (const float*)d_in[1];
    const float* V = (const float*)d_in[2];
    float* O = (float*)d_out;

    int B = in_sizes[0] / (S_LEN * HID);
    cudaFuncSetAttribute(swa_mma_kernel,
                         cudaFuncAttributeMaxDynamicSharedMemorySize, SMEM_TOTAL);
    dim3 grid(S_LEN / CHUNK, NH, B);
    swa_mma_kernel<<<grid, 256, SMEM_TOTAL>>>(Q, K, V, O);
}

// round 17
// speedup vs baseline: 1.1933x; 1.0325x over previous
#include <cuda_runtime.h>
#include <cuda_fp16.h>
#include <cstdint>

#define S_LEN 8192
#define HID   1024
#define NH    16
#define DH    64
#define WIN   128
#define CHUNK 192
#define NTHREADS 384
#define KEYS  448
#define ROWE  72            // fp16 elems per padded row (144 B); V cols 64-71 = ones block
#define ROWB  (ROWE * 2)
#define PLANE (KEYS * ROWB)      // 64512 B
#define SMEM_TOTAL (3 * PLANE)   // 193536 B  (K_hi, K_lo, V)
#define LOG2E 1.4426950408889634f

// ---------- PTX wrappers ----------
__device__ __forceinline__ void ldsm4(uint32_t addr, uint32_t r[4]) {
    asm volatile("ldmatrix.sync.aligned.m8n8.x4.shared.b16 {%0,%1,%2,%3}, [%4];"
        : "=r"(r[0]), "=r"(r[1]), "=r"(r[2]), "=r"(r[3]) : "r"(addr));
}
__device__ __forceinline__ void ldsm4t(uint32_t addr, uint32_t r[4]) {
    asm volatile("ldmatrix.sync.aligned.m8n8.x4.trans.shared.b16 {%0,%1,%2,%3}, [%4];"
        : "=r"(r[0]), "=r"(r[1]), "=r"(r[2]), "=r"(r[3]) : "r"(addr));
}
__device__ __forceinline__ void ldsm2t(uint32_t addr, uint32_t r[2]) {
    asm volatile("ldmatrix.sync.aligned.m8n8.x2.trans.shared.b16 {%0,%1}, [%2];"
        : "=r"(r[0]), "=r"(r[1]) : "r"(addr));
}
__device__ __forceinline__ void mma16816h(float* c, const uint32_t* a, uint32_t b0, uint32_t b1) {
    asm volatile("mma.sync.aligned.m16n8k16.row.col.f32.f16.f16.f32 "
        "{%0,%1,%2,%3}, {%4,%5,%6,%7}, {%8,%9}, {%0,%1,%2,%3};"
        : "+f"(c[0]), "+f"(c[1]), "+f"(c[2]), "+f"(c[3])
        : "r"(a[0]), "r"(a[1]), "r"(a[2]), "r"(a[3]), "r"(b0), "r"(b1));
}
__device__ __forceinline__ float ex2(float x) {
    float y; asm("ex2.approx.f32 %0, %1;" : "=f"(y) : "f"(x)); return y;
}
// exp2 of two floats -> packed fp16x2 (x0 in low half). -inf -> +0.
__device__ __forceinline__ uint32_t exp2h2(float x0, float x1) {
    __half2 h2 = __floats2half2_rn(x0, x1);
    uint32_t x = *reinterpret_cast<uint32_t*>(&h2), y;
    asm("ex2.approx.f16x2 %0, %1;" : "=r"(y) : "r"(x));
    return y;
}
// split two floats into packed-fp16 hi word + residual lo word (x0 in low half)
__device__ __forceinline__ void split_pack_h(float x0, float x1, uint32_t& hi, uint32_t& lo) {
    __half2 h2 = __floats2half2_rn(x0, x1);
    float2  bk = __half22float2(h2);
    __half2 l2 = __floats2half2_rn(x0 - bk.x, x1 - bk.y);
    hi = *reinterpret_cast<uint32_t*>(&h2);
    lo = *reinterpret_cast<uint32_t*>(&l2);
}
__device__ __forceinline__ uint32_t pack_h(float x0, float x1) {
    __half2 h2 = __floats2half2_rn(x0, x1);
    return *reinterpret_cast<uint32_t*>(&h2);
}

extern __shared__ char sm[];

// ---- QK of one 32-key tile into S (zeroed here), fp16 3-term ----
#define QK_TILE(S, TI) do {                                                     \
    const int kloc0q = (t0 + (TI)) * 32;                                        \
    _Pragma("unroll")                                                           \
    for (int j = 0; j < 4; j++)                                                 \
        _Pragma("unroll")                                                       \
        for (int r = 0; r < 4; r++) S[j][r] = 0.f;                              \
    _Pragma("unroll")                                                           \
    for (int kg = 0; kg < 4; kg++) {                                            \
        _Pragma("unroll")                                                       \
        for (int np = 0; np < 2; np++) {                                        \
            int keyrow = kloc0q + np * 16 + (mm >> 1) * 8 + lm7;                \
            int dim    = kg * 16 + (mm & 1) * 8;                                \
            uint32_t off = (uint32_t)(keyrow * ROWB + dim * 2);                 \
            uint32_t kbh[4], kbl[4];                                            \
            ldsm4(K_HI + off, kbh);                                             \
            ldsm4(K_LO + off, kbl);                                             \
            mma16816h(S[2*np],   aqh[kg], kbh[0], kbh[1]);                      \
            mma16816h(S[2*np],   aql[kg], kbh[0], kbh[1]);                      \
            mma16816h(S[2*np],   aqh[kg], kbl[0], kbl[1]);                      \
            mma16816h(S[2*np+1], aqh[kg], kbh[2], kbh[3]);                      \
            mma16816h(S[2*np+1], aql[kg], kbh[2], kbh[3]);                      \
            mma16816h(S[2*np+1], aqh[kg], kbl[2], kbl[3]);                      \
        }                                                                       \
    }                                                                           \
} while (0)

// ---- mask one tile's scores (edge tiles only do work) ----
#define MASK_S(S, TI) do {                                                      \
    const int kabs_m = base + (t0 + (TI)) * 32;                                 \
    const bool edge = ((TI) == 0) | ((TI) == 8) | (kabs_m < 0) | (kabs_m + 31 >= S_LEN) \
                      | (qa0 + 15 >= S_LEN);                                    \
    if (edge) {                                                                 \
        _Pragma("unroll")                                                       \
        for (int j = 0; j < 4; j++) {                                           \
            _Pragma("unroll")                                                   \
            for (int r = 0; r < 4; r++) {                                       \
                int key  = kabs_m + 8 * j + 2 * tt + (r & 1);                   \
                int qrow = qa0 + g + ((r >> 1) << 3);                           \
                bool valid = (key >= 0) && (key < S_LEN) &&                     \
                             (key >= qrow - WIN) && (key <= qrow + WIN);        \
                if (!valid) S[j][r] = -1e30f;                                   \
            }                                                                   \
        }                                                                       \
    }                                                                           \
} while (0)

// ---- fmax tree over one tile into mt0/mt1 (accumulating) ----
#define MAXTREE(S, MT0, MT1) do {                                               \
    MT0 = fmaxf(MT0, fmaxf(fmaxf(S[0][0], S[0][1]), fmaxf(S[1][0], S[1][1]))); \
    MT1 = fmaxf(MT1, fmaxf(fmaxf(S[0][2], S[0][3]), fmaxf(S[1][2], S[1][3]))); \
    MT0 = fmaxf(MT0, fmaxf(fmaxf(S[2][0], S[2][1]), fmaxf(S[3][0], S[3][1]))); \
    MT1 = fmaxf(MT1, fmaxf(fmaxf(S[2][2], S[2][3]), fmaxf(S[3][2], S[3][3]))); \
} while (0)

// ---- finish max: shfl-reduce, update running max, rescale O and of9 ----
#define FINMAX(MT0, MT1) do {                                                   \
    MT0 = fmaxf(MT0, __shfl_xor_sync(0xffffffffu, MT0, 1));                     \
    MT1 = fmaxf(MT1, __shfl_xor_sync(0xffffffffu, MT1, 1));                     \
    MT0 = fmaxf(MT0, __shfl_xor_sync(0xffffffffu, MT0, 2));                     \
    MT1 = fmaxf(MT1, __shfl_xor_sync(0xffffffffu, MT1, 2));                     \
    mn0 = fmaxf(mx[0], MT0); mn1 = fmaxf(mx[1], MT1);                           \
    const float sc0 = ex2(mx[0] - mn0), sc1 = ex2(mx[1] - mn1);                 \
    mx[0] = mn0; mx[1] = mn1;                                                   \
    _Pragma("unroll")                                                           \
    for (int j = 0; j < 8; j++) {                                               \
        of[j][0] *= sc0; of[j][1] *= sc0;                                       \
        of[j][2] *= sc1; of[j][3] *= sc1;                                       \
    }                                                                           \
    of9[0] *= sc0; of9[1] *= sc0; of9[2] *= sc1; of9[3] *= sc1;                 \
} while (0)

// ---- exp (fp16x2) + PV incl. ones-column rowsum block ----
#define EXPPV(S, TI) do {                                                       \
    const int kloc0p = (t0 + (TI)) * 32;                                        \
    uint32_t pah[2][4];                                                         \
    _Pragma("unroll")                                                           \
    for (int kg = 0; kg < 2; kg++) {                                            \
        pah[kg][0] = exp2h2(S[2*kg][0]   - mn0, S[2*kg][1]   - mn0);            \
        pah[kg][1] = exp2h2(S[2*kg][2]   - mn1, S[2*kg][3]   - mn1);            \
        pah[kg][2] = exp2h2(S[2*kg+1][0] - mn0, S[2*kg+1][1] - mn0);            \
        pah[kg][3] = exp2h2(S[2*kg+1][2] - mn1, S[2*kg+1][3] - mn1);            \
    }                                                                           \
    _Pragma("unroll")                                                           \
    for (int kg = 0; kg < 2; kg++) {                                            \
        _Pragma("unroll")                                                       \
        for (int jp = 0; jp < 4; jp++) {                                        \
            int keyrow = kloc0p + kg * 16 + (mm & 1) * 8 + lm7;                 \
            int dim    = (jp * 2 + (mm >> 1)) * 8;                              \
            uint32_t off = (uint32_t)(keyrow * ROWB + dim * 2);                 \
            uint32_t vb[4];                                                     \
            ldsm4t(V_PL + off, vb);                                             \
            mma16816h(of[2*jp],   pah[kg], vb[0], vb[1]);                       \
            mma16816h(of[2*jp+1], pah[kg], vb[2], vb[3]);                       \
        }                                                                       \
        uint32_t vb2[2];                                                        \
        ldsm2t(V_PL + (uint32_t)((kloc0p + kg * 16 + (lane & 15)) * ROWB + 128), vb2); \
        mma16816h(of9, pah[kg], vb2[0], vb2[1]);                                \
    }                                                                           \
} while (0)

__global__ __launch_bounds__(NTHREADS, 1)
void swa_mma_kernel(const float* __restrict__ Q, const float* __restrict__ K,
                    const float* __restrict__ V, float* __restrict__ O) {
    const int tid  = threadIdx.x;
    const int warp = tid >> 5;
    const int lane = tid & 31;
    const int g    = lane >> 2;
    const int tt   = lane & 3;
    const int mm   = lane >> 3;
    const int lm7  = lane & 7;

    const int c = blockIdx.x, h = blockIdx.y, b = blockIdx.z;
    const int cb = c * CHUNK;
    const int base = cb - WIN;

    const uint32_t SB   = (uint32_t)__cvta_generic_to_shared(sm);
    const uint32_t K_HI = SB;
    const uint32_t K_LO = SB + PLANE;
    const uint32_t V_PL = SB + 2 * PLANE;

    // ---------------- Q fragments: gmem -> regs, scaled by log2e (split fp16) ----------------
    // rows clamped for the tail CTA (stores are guarded)
    uint32_t aqh[4][4], aql[4][4];
    {
        const int qrow = cb + warp * 16 + g;
        const int r0 = qrow < S_LEN ? qrow : S_LEN - 1;
        const int r1 = qrow + 8 < S_LEN ? qrow + 8 : S_LEN - 1;
        const float* qp0 = Q + ((size_t)(b * S_LEN + r0) * HID) + h * DH;
        const float* qp1 = Q + ((size_t)(b * S_LEN + r1) * HID) + h * DH;
        #pragma unroll
        for (int kg = 0; kg < 4; kg++) {
            const int col0 = kg * 16 + 2 * tt;
            float2 x0 = *(const float2*)(qp0 + col0);
            float2 x1 = *(const float2*)(qp1 + col0);
            float2 x2 = *(const float2*)(qp0 + col0 + 8);
            float2 x3 = *(const float2*)(qp1 + col0 + 8);
            split_pack_h(x0.x * LOG2E, x0.y * LOG2E, aqh[kg][0], aql[kg][0]);
            split_pack_h(x1.x * LOG2E, x1.y * LOG2E, aqh[kg][1], aql[kg][1]);
            split_pack_h(x2.x * LOG2E, x2.y * LOG2E, aqh[kg][2], aql[kg][2]);
            split_pack_h(x3.x * LOG2E, x3.y * LOG2E, aqh[kg][3], aql[kg][3]);
        }
    }

    // ---------------- Stage K (hi/lo) and V (+ones col 64), zero-filled out of range ----------
    {
        #pragma unroll
        for (int it = 0; it < 19; it++) {
            int j = tid + it * NTHREADS;
            if (j < KEYS * 16) {
                int row = j >> 4;
                int c4  = (j & 15) * 4;
                int key = base + row;
                float4 k4 = make_float4(0.f, 0.f, 0.f, 0.f), v4 = k4;
                if (key >= 0 && key < S_LEN) {
                    size_t off = ((size_t)(b * S_LEN + key) * HID) + h * DH + c4;
                    k4 = *(const float4*)(K + off);
                    v4 = *(const float4*)(V + off);
                }
                int so = row * ROWB + c4 * 2;
                uint32_t h0, l0, h1, l1;
                split_pack_h(k4.x, k4.y, h0, l0);
                split_pack_h(k4.z, k4.w, h1, l1);
                *(uint2*)(sm + so)         = make_uint2(h0, h1);
                *(uint2*)(sm + PLANE + so) = make_uint2(l0, l1);
                *(uint2*)(sm + 2 * PLANE + so) =
                    make_uint2(pack_h(v4.x, v4.y), pack_h(v4.z, v4.w));
                if ((j & 15) == 15)   // ones block: col64 = 1.0h, cols 65-71 = 0
                    *(uint4*)(sm + 2 * PLANE + row * ROWB + 128) = make_uint4(0x3C00u, 0u, 0u, 0u);
            }
        }
    }
    __syncthreads();

    // ---------------- Main loop: pairs share max/rescale; rowsum via ones column -------------
    float of[8][4];
    #pragma unroll
    for (int j = 0; j < 8; j++)
        #pragma unroll
        for (int r = 0; r < 4; r++) of[j][r] = 0.f;
    float of9[4] = {0.f, 0.f, 0.f, 0.f};
    float mx[2] = {-60000.f, -60000.f};
    float mn0, mn1;

    const int t0  = warp >> 1;
    const int qa0 = cb + warp * 16;

    float sA[4][4], sB[4][4];

    QK_TILE(sA, 0);
    #pragma unroll 1
    for (int ii = 0; ii < 4; ii++) {
        QK_TILE(sB, 2 * ii + 1);
        MASK_S(sA, 2 * ii);
        MASK_S(sB, 2 * ii + 1);
        {
            float mt0 = -1e30f, mt1 = -1e30f;
            MAXTREE(sA, mt0, mt1);
            MAXTREE(sB, mt0, mt1);
            FINMAX(mt0, mt1);
        }
        EXPPV(sA, 2 * ii);
        QK_TILE(sA, 2 * ii + 2);
        EXPPV(sB, 2 * ii + 1);
    }
    MASK_S(sA, 8);
    {
        float mt0 = -1e30f, mt1 = -1e30f;
        MAXTREE(sA, mt0, mt1);
        FINMAX(mt0, mt1);
    }
    EXPPV(sA, 8);

    // ---------------- Epilogue: rowsum from ones column; guarded stores ----------------------
    const float l_lo = __shfl_sync(0xffffffffu, of9[0], lane & 28);
    const float l_hi = __shfl_sync(0xffffffffu, of9[2], lane & 28);
    const float inv_lo = 1.f / l_lo;
    const float inv_hi = 1.f / l_hi;

    const int q_lo = qa0 + g;
    const int q_hi = q_lo + 8;
    if (q_lo < S_LEN) {
        #pragma unroll
        for (int j = 0; j < 8; j++) {
            int col = h * DH + 8 * j + 2 * tt;
            size_t off_lo = ((size_t)(b * S_LEN + q_lo) * HID) + col;
            *(float2*)(O + off_lo) = make_float2(of[j][0] * inv_lo, of[j][1] * inv_lo);
        }
    }
    if (q_hi < S_LEN) {
        #pragma unroll
        for (int j = 0; j < 8; j++) {
            int col = h * DH + 8 * j + 2 * tt;
            size_t off_hi = ((size_t)(b * S_LEN + q_hi) * HID) + col;
            *(float2*)(O + off_hi) = make_float2(of[j][2] * inv_hi, of[j][3] * inv_hi);
        }
    }
}

extern "C" void kernel_launch(void* const* d_in, const int* in_sizes, int n_in,
                              void* d_out, int out_size) {
    (void)n_in; (void)out_size;
    const float* Q = (const float*)d_in[0];
    const float* K = (const float*)d_in[1];
    const float* V = (const float*)d_in[2];
    float* O = (float*)d_out;

    int B = in_sizes[0] / (S_LEN * HID);
    cudaFuncSetAttribute(swa_mma_kernel,
                         cudaFuncAttributeMaxDynamicSharedMemorySize, SMEM_TOTAL);
    dim3 grid((S_LEN + CHUNK - 1) / CHUNK, NH, B);
    swa_mma_kernel<<<grid, NTHREADS, SMEM_TOTAL>>>(Q, K, V, O);
}